// round 4
// baseline (speedup 1.0000x reference)
#include <cuda_runtime.h>
#include <stdint.h>
#include <math.h>

#define B_  16
#define N_  1024
#define D_  768
#define H_  12
#define HD_ 64
#define M_  (B_ * N_)            // 16384
#define SCALE_  0.03608439182435161f          // 1/sqrt(768)
#define SCALE2_ 0.05205928822087216f          // SCALE_ * log2(e)
#define NK_ (D_ / 32)            // 24 k-iters

// ---- device scratch (no allocation in kernel_launch) ----
__device__ uint32_t g_xt[M_ * D_];            // X in tf32
__device__ uint32_t g_wqkvt[3 * D_ * D_];     // W_{q,k,v}^T  [n=2304][k=768] tf32
__device__ uint32_t g_wot[D_ * D_];           // W_o^T        [n][k] tf32
__device__ float    g_bqkv[3 * D_];
__device__ uint32_t g_q[B_ * H_ * N_ * HD_];  // [b][h][n][d] tf32 (scale*log2e folded)
__device__ uint32_t g_k[B_ * H_ * N_ * HD_];  // [b][h][n][d] tf32
__device__ uint32_t g_v[B_ * H_ * HD_ * N_];  // [b][h][d][n] tf32 (transposed)
__device__ uint32_t g_ao[M_ * D_];            // attn out, tf32

// ---------------------------------------------------------------------------
__device__ __forceinline__ uint32_t f2tf(float f) {
    uint32_t u;
    asm("cvt.rna.tf32.f32 %0, %1;" : "=r"(u) : "f"(f));
    return u;
}
__device__ __forceinline__ void mma8(float c[4], const uint32_t a[4], const uint32_t b[2]) {
    asm volatile(
        "mma.sync.aligned.m16n8k8.row.col.f32.tf32.tf32.f32 "
        "{%0,%1,%2,%3}, {%4,%5,%6,%7}, {%8,%9}, {%0,%1,%2,%3};"
        : "+f"(c[0]), "+f"(c[1]), "+f"(c[2]), "+f"(c[3])
        : "r"(a[0]), "r"(a[1]), "r"(a[2]), "r"(a[3]), "r"(b[0]), "r"(b[1]));
}
__device__ __forceinline__ uint32_t smaddr(const void* p) {
    return (uint32_t)__cvta_generic_to_shared(p);
}
__device__ __forceinline__ void ldsm4(uint32_t r[4], const void* p) {
    uint32_t a = smaddr(p);
    asm volatile("ldmatrix.sync.aligned.m8n8.x4.shared.b16 {%0,%1,%2,%3}, [%4];"
                 : "=r"(r[0]), "=r"(r[1]), "=r"(r[2]), "=r"(r[3]) : "r"(a));
}
__device__ __forceinline__ void cp16(void* sp, const void* gp) {
    asm volatile("cp.async.cg.shared.global [%0], [%1], 16;"
                 :: "r"(smaddr(sp)), "l"(gp));
}
#define CP_COMMIT asm volatile("cp.async.commit_group;")
#define CP_WAIT0  asm volatile("cp.async.wait_group 0;")
#define CP_WAIT1  asm volatile("cp.async.wait_group 1;")

// ---------------------------------------------------------------------------
// prep kernels (one-time)
// ---------------------------------------------------------------------------
__global__ void prep_x(const float* __restrict__ X, uint32_t* __restrict__ Xt) {
    size_t i = ((size_t)blockIdx.x * 256 + threadIdx.x) * 4;
    float4 v = *(const float4*)(X + i);
    *(uint4*)(Xt + i) = make_uint4(f2tf(v.x), f2tf(v.y), f2tf(v.z), f2tf(v.w));
}

__global__ void prep_w(const float* __restrict__ Wq, const float* __restrict__ Wk,
                       const float* __restrict__ Wv, const float* __restrict__ Wo,
                       uint32_t* __restrict__ Wqkvt, uint32_t* __restrict__ Wot) {
    __shared__ float t[32][33];
    const int z = blockIdx.z;
    const float* src = (z == 0) ? Wq : (z == 1) ? Wk : (z == 2) ? Wv : Wo;
    uint32_t* dst = (z < 3) ? (Wqkvt + (size_t)z * D_ * D_) : Wot;
    const int x0 = blockIdx.x * 32;   // n
    const int y0 = blockIdx.y * 32;   // k
    const int tx = threadIdx.x, ty = threadIdx.y;
#pragma unroll
    for (int r = 0; r < 4; r++)
        t[ty + 8 * r][tx] = src[(size_t)(y0 + ty + 8 * r) * D_ + x0 + tx];
    __syncthreads();
#pragma unroll
    for (int r = 0; r < 4; r++)
        dst[(size_t)(x0 + ty + 8 * r) * D_ + y0 + tx] = f2tf(t[tx][ty + 8 * r]);
}

__global__ void prep_b(const float* bq, const float* bk, const float* bv, float* bqkv) {
    int i = threadIdx.x;
    bqkv[i] = bq[i]; bqkv[D_ + i] = bk[i]; bqkv[2 * D_ + i] = bv[i];
}

// ---------------------------------------------------------------------------
// GEMM: C = A(tf32 [M][768]) @ Bt(tf32 [N][768])^T + bias
// CTA 128x128x32, double-buffered cp.async, 256 threads (8 warps 2x4),
// warp tile 64x32.
// MODE 1: fused QKV epilogue -> g_q (scaled) / g_k / g_v(transposed), tf32.
// MODE 0: f32 out + bias (final projection).
// ---------------------------------------------------------------------------
#define GS 36
#define GEMM_SMEM (4 * 128 * GS * 4)   // 73728 B

template <int MODE>
__global__ __launch_bounds__(256, 2)
void gemm2(const uint32_t* __restrict__ A, const uint32_t* __restrict__ Bt,
           const float* __restrict__ bias, float* __restrict__ outF,
           uint32_t* __restrict__ oq, uint32_t* __restrict__ ok,
           uint32_t* __restrict__ ov)
{
    extern __shared__ uint32_t sg[];
    uint32_t* As = sg;                // [2][128*GS]
    uint32_t* Bs = sg + 2 * 128 * GS;

    const int tid  = threadIdx.x;
    const int lane = tid & 31;
    const int wid  = tid >> 5;
    const int wm   = (wid >> 2) * 64;   // 0,64
    const int wn   = (wid & 3) * 32;    // 0,32,64,96
    const int m0   = blockIdx.y * 128;
    const int n0   = blockIdx.x * 128;

    // staging: 32 rows x 8 k-chunks per pass, 4 passes
    const int lr = tid >> 3;             // 0..31
    const int lk = (tid & 7) << 2;       // 0..28
    const uint32_t* Ap = A  + (size_t)(m0 + lr) * D_ + lk;
    const uint32_t* Bp = Bt + (size_t)(n0 + lr) * D_ + lk;

    float acc[4][4][4];
#pragma unroll
    for (int i = 0; i < 4; i++)
#pragma unroll
        for (int j = 0; j < 4; j++)
#pragma unroll
            for (int r = 0; r < 4; r++) acc[i][j][r] = 0.f;

    {
#pragma unroll
        for (int p = 0; p < 4; p++) {
            cp16(&As[(lr + 32 * p) * GS + lk], Ap + (size_t)32 * p * D_);
            cp16(&Bs[(lr + 32 * p) * GS + lk], Bp + (size_t)32 * p * D_);
        }
        CP_COMMIT;
    }

    int buf = 0;
    for (int it = 0; it < NK_; it++) {
        __syncthreads();
        if (it + 1 < NK_) {
            uint32_t* as = As + (buf ^ 1) * 128 * GS;
            uint32_t* bs = Bs + (buf ^ 1) * 128 * GS;
            const uint32_t* ap = Ap + (size_t)(it + 1) * 32;
            const uint32_t* bp = Bp + (size_t)(it + 1) * 32;
#pragma unroll
            for (int p = 0; p < 4; p++) {
                cp16(&as[(lr + 32 * p) * GS + lk], ap + (size_t)32 * p * D_);
                cp16(&bs[(lr + 32 * p) * GS + lk], bp + (size_t)32 * p * D_);
            }
            CP_COMMIT;
            CP_WAIT1;
        } else {
            CP_WAIT0;
        }
        __syncthreads();

        const uint32_t* as = As + buf * 128 * GS;
        const uint32_t* bs = Bs + buf * 128 * GS;
#pragma unroll
        for (int kk = 0; kk < 4; kk++) {
            const int kb = kk * 8;
            uint32_t af[4][4];
#pragma unroll
            for (int i = 0; i < 4; i++)
                ldsm4(af[i], &as[(wm + i * 16 + (lane & 15)) * GS + kb + 4 * (lane >> 4)]);
            uint32_t bf[2][4];
#pragma unroll
            for (int jj = 0; jj < 2; jj++)
                ldsm4(bf[jj], &bs[(wn + jj * 16 + ((lane >> 4) << 3) + (lane & 7)) * GS
                                  + kb + 4 * ((lane >> 3) & 1)]);
#pragma unroll
            for (int i = 0; i < 4; i++)
#pragma unroll
                for (int jj = 0; jj < 2; jj++) {
                    mma8(acc[i][2 * jj],     af[i], &bf[jj][0]);
                    mma8(acc[i][2 * jj + 1], af[i], &bf[jj][2]);
                }
        }
        buf ^= 1;
    }

    // epilogue
    const int mrow0 = m0 + wm + (lane >> 2);
    const int col0  = n0 + wn + 2 * (lane & 3);
#pragma unroll
    for (int i = 0; i < 4; i++) {
#pragma unroll
        for (int j = 0; j < 4; j++) {
            const int row = mrow0 + i * 16;
            const int col = col0 + j * 8;
            const float2 bv = *(const float2*)(bias + col);
            float c0 = acc[i][j][0] + bv.x, c1 = acc[i][j][1] + bv.y;
            float c2 = acc[i][j][2] + bv.x, c3 = acc[i][j][3] + bv.y;
            if (MODE == 0) {
                *(float2*)(outF + (size_t)row * D_ + col)       = make_float2(c0, c1);
                *(float2*)(outF + (size_t)(row + 8) * D_ + col) = make_float2(c2, c3);
            } else {
                const int which = n0 / D_;        // uniform per CTA
                const int ncol  = col - which * D_;
                const int h = ncol >> 6, d = ncol & 63;
                const int b = row >> 10, r = row & 1023;
                if (which == 0) {
                    // Q: fold attention scale * log2(e)
                    uint2 u0 = make_uint2(f2tf(c0 * SCALE2_), f2tf(c1 * SCALE2_));
                    uint2 u1 = make_uint2(f2tf(c2 * SCALE2_), f2tf(c3 * SCALE2_));
                    uint32_t* base = oq + ((((size_t)b * H_ + h) * N_) + r) * HD_ + d;
                    *(uint2*)base = u0; *(uint2*)(base + 8 * HD_) = u1;
                } else if (which == 1) {
                    uint2 u0 = make_uint2(f2tf(c0), f2tf(c1));
                    uint2 u1 = make_uint2(f2tf(c2), f2tf(c3));
                    uint32_t* base = ok + ((((size_t)b * H_ + h) * N_) + r) * HD_ + d;
                    *(uint2*)base = u0; *(uint2*)(base + 8 * HD_) = u1;
                } else {
                    // V transposed: [b][h][d][key]
                    uint32_t* base = ov + (((size_t)b * H_ + h) * HD_ + d) * N_ + r;
                    base[0]      = f2tf(c0);
                    base[N_]     = f2tf(c1);
                    base[8]      = f2tf(c2);
                    base[N_ + 8] = f2tf(c3);
                }
            }
        }
    }
}

// ---------------------------------------------------------------------------
// Flash attention: CTA = 128 q rows, 256 threads (8 warps x 16 q rows).
// 64-key tiles; softmax in exp2 domain (log2e folded into Q).
// smem: Qs[128][68], KP[128][68] (K rows 0-63, later P rows 0-127), Vt[64][68].
// ---------------------------------------------------------------------------
#define AS 68
#define ATTN_SMEM ((128 + 128 + 64) * AS * 4)   // 87040 B

__global__ __launch_bounds__(256, 2)
void attn2(const uint32_t* __restrict__ Q, const uint32_t* __restrict__ K,
           const uint32_t* __restrict__ V, uint32_t* __restrict__ O)
{
    extern __shared__ uint32_t sm[];
    uint32_t* Qs = sm;                  // [128][AS]
    uint32_t* KP = sm + 128 * AS;       // K rows 0-63 -> later P rows 0-127
    uint32_t* Vt = sm + 256 * AS;       // [d=64][AS]

    const int tid  = threadIdx.x;
    const int lane = tid & 31;
    const int wid  = tid >> 5;
    const int b    = blockIdx.z;
    const int h    = blockIdx.y;
    const int q0   = blockIdx.x * 128;

    const uint32_t* Qb = Q + (((size_t)b * H_ + h) * N_ + q0) * HD_;
    const uint32_t* Kb = K + (((size_t)b * H_ + h) * N_) * HD_;
    const uint32_t* Vb = V + (((size_t)b * H_ + h) * HD_) * N_;

    const int fr = tid >> 4;              // 0..15
    const int fc = (tid & 15) << 2;       // 0..60

    // fill Q tile (128x64)
#pragma unroll
    for (int p = 0; p < 8; p++) {
        const int row = fr + 16 * p;
        cp16(&Qs[row * AS + fc], Qb + (size_t)row * HD_ + fc);
    }
    CP_COMMIT;

    float oa[8][4];
    float m0s = -1e30f, m1s = -1e30f, l0s = 0.f, l1s = 0.f;
#pragma unroll
    for (int nt = 0; nt < 8; nt++)
#pragma unroll
        for (int r = 0; r < 4; r++) oa[nt][r] = 0.f;

    const int qbase = wid * 16;

    for (int t = 0; t < N_ / 64; t++) {
        // fill K tile [key][d] and Vt tile [d][key]
        const uint32_t* Kt  = Kb + (size_t)t * 64 * HD_;
        const uint32_t* Vtg = Vb + (size_t)t * 64;
#pragma unroll
        for (int p = 0; p < 4; p++) {
            const int row = fr + 16 * p;
            cp16(&KP[row * AS + fc], Kt + (size_t)row * HD_ + fc);
            cp16(&Vt[row * AS + fc], Vtg + (size_t)row * N_ + fc);
        }
        CP_COMMIT; CP_WAIT0;
        __syncthreads();

        // ---- S = Q K^T (16 q x 64 keys per warp) ----
        float sa[8][4];
#pragma unroll
        for (int nt = 0; nt < 8; nt++)
#pragma unroll
            for (int r = 0; r < 4; r++) sa[nt][r] = 0.f;

#pragma unroll
        for (int kk = 0; kk < 8; kk++) {
            const int kb = kk * 8;
            uint32_t qa[4];
            ldsm4(qa, &Qs[(qbase + (lane & 15)) * AS + kb + 4 * (lane >> 4)]);
            uint32_t kf[4][4];
#pragma unroll
            for (int jj = 0; jj < 4; jj++)
                ldsm4(kf[jj], &KP[(jj * 16 + ((lane >> 4) << 3) + (lane & 7)) * AS
                                  + kb + 4 * ((lane >> 3) & 1)]);
#pragma unroll
            for (int jj = 0; jj < 4; jj++) {
                mma8(sa[2 * jj],     qa, &kf[jj][0]);
                mma8(sa[2 * jj + 1], qa, &kf[jj][2]);
            }
        }

        // ---- online softmax in exp2 domain ----
        float tm0 = -1e30f, tm1 = -1e30f;
#pragma unroll
        for (int nt = 0; nt < 8; nt++) {
            tm0 = fmaxf(tm0, fmaxf(sa[nt][0], sa[nt][1]));
            tm1 = fmaxf(tm1, fmaxf(sa[nt][2], sa[nt][3]));
        }
        tm0 = fmaxf(tm0, __shfl_xor_sync(0xffffffffu, tm0, 1));
        tm0 = fmaxf(tm0, __shfl_xor_sync(0xffffffffu, tm0, 2));
        tm1 = fmaxf(tm1, __shfl_xor_sync(0xffffffffu, tm1, 1));
        tm1 = fmaxf(tm1, __shfl_xor_sync(0xffffffffu, tm1, 2));

        const float mn0 = fmaxf(m0s, tm0);
        const float mn1 = fmaxf(m1s, tm1);
        const float c0 = exp2f(m0s - mn0);
        const float c1 = exp2f(m1s - mn1);
        m0s = mn0; m1s = mn1;

        float rs0 = 0.f, rs1 = 0.f;
#pragma unroll
        for (int nt = 0; nt < 8; nt++) {
            sa[nt][0] = exp2f(sa[nt][0] - mn0); rs0 += sa[nt][0];
            sa[nt][1] = exp2f(sa[nt][1] - mn0); rs0 += sa[nt][1];
            sa[nt][2] = exp2f(sa[nt][2] - mn1); rs1 += sa[nt][2];
            sa[nt][3] = exp2f(sa[nt][3] - mn1); rs1 += sa[nt][3];
        }
        rs0 += __shfl_xor_sync(0xffffffffu, rs0, 1);
        rs0 += __shfl_xor_sync(0xffffffffu, rs0, 2);
        rs1 += __shfl_xor_sync(0xffffffffu, rs1, 1);
        rs1 += __shfl_xor_sync(0xffffffffu, rs1, 2);

        l0s = l0s * c0 + rs0;
        l1s = l1s * c1 + rs1;
#pragma unroll
        for (int nt = 0; nt < 8; nt++) {
            oa[nt][0] *= c0; oa[nt][1] *= c0;
            oa[nt][2] *= c1; oa[nt][3] *= c1;
        }

        __syncthreads();   // all warps done reading K rows of KP

        // ---- write P (tf32) into KP [q 0-127][key 0-63] ----
        {
            const int row = qbase + (lane >> 2);
#pragma unroll
            for (int nt = 0; nt < 8; nt++) {
                const int col = nt * 8 + 2 * (lane & 3);
                *(uint2*)&KP[row * AS + col] =
                    make_uint2(f2tf(sa[nt][0]), f2tf(sa[nt][1]));
                *(uint2*)&KP[(row + 8) * AS + col] =
                    make_uint2(f2tf(sa[nt][2]), f2tf(sa[nt][3]));
            }
        }
        __syncwarp();      // warp reads back only its own 16 P rows

        // ---- O += P @ V ----
#pragma unroll
        for (int kk = 0; kk < 8; kk++) {
            const int kb = kk * 8;
            uint32_t pa[4];
            ldsm4(pa, &KP[(qbase + (lane & 15)) * AS + kb + 4 * (lane >> 4)]);
            uint32_t vf[4][4];
#pragma unroll
            for (int jj = 0; jj < 4; jj++)
                ldsm4(vf[jj], &Vt[(jj * 16 + ((lane >> 4) << 3) + (lane & 7)) * AS
                                  + kb + 4 * ((lane >> 3) & 1)]);
#pragma unroll
            for (int jj = 0; jj < 4; jj++) {
                mma8(oa[2 * jj],     pa, &vf[jj][0]);
                mma8(oa[2 * jj + 1], pa, &vf[jj][2]);
            }
        }
        __syncthreads();   // PV reads done before next-iter K/Vt refill
    }

    // ---- normalize + store tf32 into g_ao [M][768] ----
    const float inv0 = 1.f / l0s;
    const float inv1 = 1.f / l1s;
    const int row = b * N_ + q0 + qbase + (lane >> 2);
    uint32_t* Op = O + (size_t)row * D_ + h * HD_;
#pragma unroll
    for (int nt = 0; nt < 8; nt++) {
        const int cc = nt * 8 + 2 * (lane & 3);
        *(uint2*)(Op + cc) =
            make_uint2(f2tf(oa[nt][0] * inv0), f2tf(oa[nt][1] * inv0));
        *(uint2*)(Op + (size_t)8 * D_ + cc) =
            make_uint2(f2tf(oa[nt][2] * inv1), f2tf(oa[nt][3] * inv1));
    }
}

// ---------------------------------------------------------------------------
extern "C" void kernel_launch(void* const* d_in, const int* in_sizes, int n_in,
                              void* d_out, int out_size)
{
    const float* X  = (const float*)d_in[0];
    const float* Wq = (const float*)d_in[1];
    const float* bq = (const float*)d_in[2];
    const float* Wk = (const float*)d_in[3];
    const float* bk = (const float*)d_in[4];
    const float* Wv = (const float*)d_in[5];
    const float* bv = (const float*)d_in[6];
    const float* Wo = (const float*)d_in[7];
    const float* bo = (const float*)d_in[8];
    float* out = (float*)d_out;

    uint32_t *xt, *wqkvt, *wot, *qp, *kp, *vp, *aop;
    float* bqkv;
    cudaGetSymbolAddress((void**)&xt,    g_xt);
    cudaGetSymbolAddress((void**)&wqkvt, g_wqkvt);
    cudaGetSymbolAddress((void**)&wot,   g_wot);
    cudaGetSymbolAddress((void**)&bqkv,  g_bqkv);
    cudaGetSymbolAddress((void**)&qp,    g_q);
    cudaGetSymbolAddress((void**)&kp,    g_k);
    cudaGetSymbolAddress((void**)&vp,    g_v);
    cudaGetSymbolAddress((void**)&aop,   g_ao);

    cudaFuncSetAttribute(gemm2<1>, cudaFuncAttributeMaxDynamicSharedMemorySize, GEMM_SMEM);
    cudaFuncSetAttribute(gemm2<0>, cudaFuncAttributeMaxDynamicSharedMemorySize, GEMM_SMEM);
    cudaFuncSetAttribute(attn2,    cudaFuncAttributeMaxDynamicSharedMemorySize, ATTN_SMEM);

    prep_x<<<M_ * D_ / 1024, 256>>>(X, xt);
    prep_w<<<dim3(24, 24, 4), dim3(32, 8)>>>(Wq, Wk, Wv, Wo, wqkvt, wot);
    prep_b<<<1, D_>>>(bq, bk, bv, bqkv);

    gemm2<1><<<dim3(3 * D_ / 128, M_ / 128), 256, GEMM_SMEM>>>(
        xt, wqkvt, bqkv, nullptr, qp, kp, vp);

    attn2<<<dim3(N_ / 128, H_, B_), 256, ATTN_SMEM>>>(qp, kp, vp, aop);

    gemm2<0><<<dim3(D_ / 128, M_ / 128), 256, GEMM_SMEM>>>(
        aop, wot, bo, out, nullptr, nullptr, nullptr);
}

// round 5
// speedup vs baseline: 1.1373x; 1.1373x over previous
#include <cuda_runtime.h>
#include <stdint.h>
#include <math.h>

#define B_  16
#define N_  1024
#define D_  768
#define H_  12
#define HD_ 64
#define M_  (B_ * N_)            // 16384
#define SCALE2_ 0.05205928822087216f   // (1/sqrt(768)) * log2(e)
#define NK_ (D_ / 32)            // 24 k-iters

// ---- device scratch (no allocation in kernel_launch) ----
__device__ uint32_t g_xt[M_ * D_];            // X in tf32
__device__ uint32_t g_wqkvt[3 * D_ * D_];     // W_{q,k,v}^T  [n=2304][k=768] tf32
__device__ uint32_t g_wot[D_ * D_];           // W_o^T        [n][k] tf32
__device__ float    g_bqkv[3 * D_];
__device__ uint32_t g_q[B_ * H_ * N_ * HD_];  // [b][h][n][d] tf32 (scale*log2e folded)
__device__ uint32_t g_k[B_ * H_ * N_ * HD_];  // [b][h][n][d] tf32
__device__ uint32_t g_v[B_ * H_ * HD_ * N_];  // [b][h][d][n] tf32 (transposed)
__device__ uint32_t g_ao[M_ * D_];            // attn out, tf32

// ---------------------------------------------------------------------------
__device__ __forceinline__ uint32_t f2tf(float f) {
    uint32_t u;
    asm("cvt.rna.tf32.f32 %0, %1;" : "=r"(u) : "f"(f));
    return u;
}
__device__ __forceinline__ void mma8(float c[4], const uint32_t a[4], const uint32_t b[2]) {
    asm volatile(
        "mma.sync.aligned.m16n8k8.row.col.f32.tf32.tf32.f32 "
        "{%0,%1,%2,%3}, {%4,%5,%6,%7}, {%8,%9}, {%0,%1,%2,%3};"
        : "+f"(c[0]), "+f"(c[1]), "+f"(c[2]), "+f"(c[3])
        : "r"(a[0]), "r"(a[1]), "r"(a[2]), "r"(a[3]), "r"(b[0]), "r"(b[1]));
}
__device__ __forceinline__ uint32_t smaddr(const void* p) {
    return (uint32_t)__cvta_generic_to_shared(p);
}
__device__ __forceinline__ void ldsm4(uint32_t r[4], const void* p) {
    uint32_t a = smaddr(p);
    asm volatile("ldmatrix.sync.aligned.m8n8.x4.shared.b16 {%0,%1,%2,%3}, [%4];"
                 : "=r"(r[0]), "=r"(r[1]), "=r"(r[2]), "=r"(r[3]) : "r"(a));
}
__device__ __forceinline__ void cp16(void* sp, const void* gp) {
    asm volatile("cp.async.cg.shared.global [%0], [%1], 16;"
                 :: "r"(smaddr(sp)), "l"(gp));
}
#define CP_COMMIT asm volatile("cp.async.commit_group;")
#define CP_WAIT0  asm volatile("cp.async.wait_group 0;")
#define CP_WAIT1  asm volatile("cp.async.wait_group 1;")

// ---------------------------------------------------------------------------
// prep kernels (one-time)
// ---------------------------------------------------------------------------
__global__ void prep_x(const float* __restrict__ X, uint32_t* __restrict__ Xt) {
    size_t i = ((size_t)blockIdx.x * 256 + threadIdx.x) * 4;
    float4 v = *(const float4*)(X + i);
    *(uint4*)(Xt + i) = make_uint4(f2tf(v.x), f2tf(v.y), f2tf(v.z), f2tf(v.w));
}

__global__ void prep_w(const float* __restrict__ Wq, const float* __restrict__ Wk,
                       const float* __restrict__ Wv, const float* __restrict__ Wo,
                       uint32_t* __restrict__ Wqkvt, uint32_t* __restrict__ Wot) {
    __shared__ float t[32][33];
    const int z = blockIdx.z;
    const float* src = (z == 0) ? Wq : (z == 1) ? Wk : (z == 2) ? Wv : Wo;
    uint32_t* dst = (z < 3) ? (Wqkvt + (size_t)z * D_ * D_) : Wot;
    const int x0 = blockIdx.x * 32;   // n
    const int y0 = blockIdx.y * 32;   // k
    const int tx = threadIdx.x, ty = threadIdx.y;
#pragma unroll
    for (int r = 0; r < 4; r++)
        t[ty + 8 * r][tx] = src[(size_t)(y0 + ty + 8 * r) * D_ + x0 + tx];
    __syncthreads();
#pragma unroll
    for (int r = 0; r < 4; r++)
        dst[(size_t)(x0 + ty + 8 * r) * D_ + y0 + tx] = f2tf(t[tx][ty + 8 * r]);
}

__global__ void prep_b(const float* bq, const float* bk, const float* bv, float* bqkv) {
    int i = threadIdx.x;
    bqkv[i] = bq[i]; bqkv[D_ + i] = bk[i]; bqkv[2 * D_ + i] = bv[i];
}

// ---------------------------------------------------------------------------
// GEMM (R3 shape): CTA 128x128x32, 128 threads (4 warps 2x2), warp tile 64x64,
// double-buffered cp.async.
// ---------------------------------------------------------------------------
#define GS 36
#define GEMM_SMEM (4 * 128 * GS * 4)   // 73728 B

template <int MODE>
__global__ __launch_bounds__(128)
void gemm2(const uint32_t* __restrict__ A, const uint32_t* __restrict__ Bt,
           const float* __restrict__ bias, float* __restrict__ outF,
           uint32_t* __restrict__ oq, uint32_t* __restrict__ ok,
           uint32_t* __restrict__ ov)
{
    extern __shared__ uint32_t sg[];
    uint32_t* As = sg;                // [2][128*GS]
    uint32_t* Bs = sg + 2 * 128 * GS;

    const int tid  = threadIdx.x;
    const int lane = tid & 31;
    const int wid  = tid >> 5;
    const int wm   = (wid >> 1) * 64;
    const int wn   = (wid & 1) * 64;
    const int m0   = blockIdx.y * 128;
    const int n0   = blockIdx.x * 128;

    const int lr = tid >> 3;             // 0..15
    const int lk = (tid & 7) << 2;       // 0..28
    const uint32_t* Ap = A  + (size_t)(m0 + lr) * D_ + lk;
    const uint32_t* Bp = Bt + (size_t)(n0 + lr) * D_ + lk;

    float acc[4][8][4];
#pragma unroll
    for (int i = 0; i < 4; i++)
#pragma unroll
        for (int j = 0; j < 8; j++)
#pragma unroll
            for (int r = 0; r < 4; r++) acc[i][j][r] = 0.f;

    {
#pragma unroll
        for (int p = 0; p < 8; p++) {
            cp16(&As[(lr + 16 * p) * GS + lk], Ap + (size_t)16 * p * D_);
            cp16(&Bs[(lr + 16 * p) * GS + lk], Bp + (size_t)16 * p * D_);
        }
        CP_COMMIT;
    }

    int buf = 0;
    for (int it = 0; it < NK_; it++) {
        __syncthreads();
        if (it + 1 < NK_) {
            uint32_t* as = As + (buf ^ 1) * 128 * GS;
            uint32_t* bs = Bs + (buf ^ 1) * 128 * GS;
            const uint32_t* ap = Ap + (size_t)(it + 1) * 32;
            const uint32_t* bp = Bp + (size_t)(it + 1) * 32;
#pragma unroll
            for (int p = 0; p < 8; p++) {
                cp16(&as[(lr + 16 * p) * GS + lk], ap + (size_t)16 * p * D_);
                cp16(&bs[(lr + 16 * p) * GS + lk], bp + (size_t)16 * p * D_);
            }
            CP_COMMIT;
            CP_WAIT1;
        } else {
            CP_WAIT0;
        }
        __syncthreads();

        const uint32_t* as = As + buf * 128 * GS;
        const uint32_t* bs = Bs + buf * 128 * GS;
#pragma unroll
        for (int kk = 0; kk < 4; kk++) {
            const int kb = kk * 8;
            uint32_t af[4][4];
#pragma unroll
            for (int i = 0; i < 4; i++)
                ldsm4(af[i], &as[(wm + i * 16 + (lane & 15)) * GS + kb + 4 * (lane >> 4)]);
            uint32_t bf[4][4];
#pragma unroll
            for (int jj = 0; jj < 4; jj++)
                ldsm4(bf[jj], &bs[(wn + jj * 16 + ((lane >> 4) << 3) + (lane & 7)) * GS
                                  + kb + 4 * ((lane >> 3) & 1)]);
#pragma unroll
            for (int i = 0; i < 4; i++)
#pragma unroll
                for (int jj = 0; jj < 4; jj++) {
                    mma8(acc[i][2 * jj],     af[i], &bf[jj][0]);
                    mma8(acc[i][2 * jj + 1], af[i], &bf[jj][2]);
                }
        }
        buf ^= 1;
    }

    const int mrow0 = m0 + wm + (lane >> 2);
    const int col0  = n0 + wn + 2 * (lane & 3);
#pragma unroll
    for (int i = 0; i < 4; i++) {
#pragma unroll
        for (int j = 0; j < 8; j++) {
            const int row = mrow0 + i * 16;
            const int col = col0 + j * 8;
            const float2 bv = *(const float2*)(bias + col);
            float c0 = acc[i][j][0] + bv.x, c1 = acc[i][j][1] + bv.y;
            float c2 = acc[i][j][2] + bv.x, c3 = acc[i][j][3] + bv.y;
            if (MODE == 0) {
                *(float2*)(outF + (size_t)row * D_ + col)       = make_float2(c0, c1);
                *(float2*)(outF + (size_t)(row + 8) * D_ + col) = make_float2(c2, c3);
            } else {
                const int which = n0 / D_;        // uniform per CTA
                const int ncol  = col - which * D_;
                const int h = ncol >> 6, d = ncol & 63;
                const int b = row >> 10, r = row & 1023;
                if (which == 0) {
                    uint2 u0 = make_uint2(f2tf(c0 * SCALE2_), f2tf(c1 * SCALE2_));
                    uint2 u1 = make_uint2(f2tf(c2 * SCALE2_), f2tf(c3 * SCALE2_));
                    uint32_t* base = oq + ((((size_t)b * H_ + h) * N_) + r) * HD_ + d;
                    *(uint2*)base = u0; *(uint2*)(base + 8 * HD_) = u1;
                } else if (which == 1) {
                    uint2 u0 = make_uint2(f2tf(c0), f2tf(c1));
                    uint2 u1 = make_uint2(f2tf(c2), f2tf(c3));
                    uint32_t* base = ok + ((((size_t)b * H_ + h) * N_) + r) * HD_ + d;
                    *(uint2*)base = u0; *(uint2*)(base + 8 * HD_) = u1;
                } else {
                    uint32_t* base = ov + (((size_t)b * H_ + h) * HD_ + d) * N_ + r;
                    base[0]      = f2tf(c0);
                    base[N_]     = f2tf(c1);
                    base[8]      = f2tf(c2);
                    base[N_ + 8] = f2tf(c3);
                }
            }
        }
    }
}

// ---------------------------------------------------------------------------
// Flash attention: CTA = 128 q rows, 128 threads (4 warps x 32 q rows).
// Double-buffered K/V tiles (cp.async overlapped with compute).
// P never touches smem: S-fragments -> PV A-fragments via quad shuffles.
// smem: Qs[128][68] + K[2][64][68] + Vt[2][64][68] = 104448 B -> 2 CTAs/SM.
// ---------------------------------------------------------------------------
#define AS 68
#define ATTN_SMEM ((128 + 2 * 64 + 2 * 64) * AS * 4)   // 104448 B

__global__ __launch_bounds__(128, 2)
void attn3(const uint32_t* __restrict__ Q, const uint32_t* __restrict__ K,
           const uint32_t* __restrict__ V, uint32_t* __restrict__ O)
{
    extern __shared__ uint32_t sm[];
    uint32_t* Qs = sm;                        // [128][AS]
    uint32_t* Kb = sm + 128 * AS;             // [2][64][AS]
    uint32_t* Vb = sm + (128 + 128) * AS;     // [2][64][AS]  ([d][key])

    const int tid  = threadIdx.x;
    const int lane = tid & 31;
    const int wid  = tid >> 5;
    const int b    = blockIdx.z;
    const int h    = blockIdx.y;
    const int q0   = blockIdx.x * 128;

    const uint32_t* Qg = Q + (((size_t)b * H_ + h) * N_ + q0) * HD_;
    const uint32_t* Kg = K + (((size_t)b * H_ + h) * N_) * HD_;
    const uint32_t* Vg = V + (((size_t)b * H_ + h) * HD_) * N_;

    const int fr = tid >> 4;              // 0..7
    const int fc = (tid & 15) << 2;       // 0..60

    // prologue: Q tile + K/V tile 0 -> buf 0, one cp group
#pragma unroll
    for (int p = 0; p < 16; p++) {
        const int row = fr + 8 * p;
        cp16(&Qs[row * AS + fc], Qg + (size_t)row * HD_ + fc);
    }
#pragma unroll
    for (int p = 0; p < 8; p++) {
        const int row = fr + 8 * p;
        cp16(&Kb[row * AS + fc], Kg + (size_t)row * HD_ + fc);
        cp16(&Vb[row * AS + fc], Vg + (size_t)row * N_ + fc);
    }
    CP_COMMIT;

    float oa[2][8][4];
    float ms[2][2], ls[2][2];
#pragma unroll
    for (int i = 0; i < 2; i++) {
        ms[i][0] = ms[i][1] = -1e30f;
        ls[i][0] = ls[i][1] = 0.f;
#pragma unroll
        for (int nt = 0; nt < 8; nt++)
#pragma unroll
            for (int r = 0; r < 4; r++) oa[i][nt][r] = 0.f;
    }

    const int qbase = wid * 32;
    // shuffle-transpose lanes (quad-local)
    const int qd  = lane & 3;
    const int lo  = (lane & ~3) | (qd >> 1);
    const int hi  = lo + 2;
    const bool odd = qd & 1;

    int buf = 0;
    for (int t = 0; t < N_ / 64; t++) {
        CP_WAIT0;
        __syncthreads();

        if (t + 1 < N_ / 64) {
            uint32_t* kd = Kb + (buf ^ 1) * 64 * AS;
            uint32_t* vd = Vb + (buf ^ 1) * 64 * AS;
            const uint32_t* kg = Kg + (size_t)(t + 1) * 64 * HD_;
            const uint32_t* vg = Vg + (size_t)(t + 1) * 64;
#pragma unroll
            for (int p = 0; p < 8; p++) {
                const int row = fr + 8 * p;
                cp16(&kd[row * AS + fc], kg + (size_t)row * HD_ + fc);
                cp16(&vd[row * AS + fc], vg + (size_t)row * N_ + fc);
            }
            CP_COMMIT;
        }

        const uint32_t* Kt = Kb + buf * 64 * AS;
        const uint32_t* Vt = Vb + buf * 64 * AS;

        // ---- S = Q K^T (32 q x 64 keys per warp) ----
        float sa[2][8][4];
#pragma unroll
        for (int i = 0; i < 2; i++)
#pragma unroll
            for (int nt = 0; nt < 8; nt++)
#pragma unroll
                for (int r = 0; r < 4; r++) sa[i][nt][r] = 0.f;

#pragma unroll
        for (int kk = 0; kk < 8; kk++) {
            const int kb = kk * 8;
            uint32_t qa[2][4];
#pragma unroll
            for (int i = 0; i < 2; i++)
                ldsm4(qa[i], &Qs[(qbase + i * 16 + (lane & 15)) * AS + kb + 4 * (lane >> 4)]);
            uint32_t kf[4][4];
#pragma unroll
            for (int jj = 0; jj < 4; jj++)
                ldsm4(kf[jj], &Kt[(jj * 16 + ((lane >> 4) << 3) + (lane & 7)) * AS
                                  + kb + 4 * ((lane >> 3) & 1)]);
#pragma unroll
            for (int i = 0; i < 2; i++)
#pragma unroll
                for (int jj = 0; jj < 4; jj++) {
                    mma8(sa[i][2 * jj],     qa[i], &kf[jj][0]);
                    mma8(sa[i][2 * jj + 1], qa[i], &kf[jj][2]);
                }
        }

        // ---- online softmax (exp2 domain; log2e folded into Q) ----
#pragma unroll
        for (int i = 0; i < 2; i++) {
            float tm0 = -1e30f, tm1 = -1e30f;
#pragma unroll
            for (int nt = 0; nt < 8; nt++) {
                tm0 = fmaxf(tm0, fmaxf(sa[i][nt][0], sa[i][nt][1]));
                tm1 = fmaxf(tm1, fmaxf(sa[i][nt][2], sa[i][nt][3]));
            }
            tm0 = fmaxf(tm0, __shfl_xor_sync(0xffffffffu, tm0, 1));
            tm0 = fmaxf(tm0, __shfl_xor_sync(0xffffffffu, tm0, 2));
            tm1 = fmaxf(tm1, __shfl_xor_sync(0xffffffffu, tm1, 1));
            tm1 = fmaxf(tm1, __shfl_xor_sync(0xffffffffu, tm1, 2));
            const float mn0 = fmaxf(ms[i][0], tm0);
            const float mn1 = fmaxf(ms[i][1], tm1);
            const float c0 = exp2f(ms[i][0] - mn0);
            const float c1 = exp2f(ms[i][1] - mn1);
            ms[i][0] = mn0; ms[i][1] = mn1;
            float rs0 = 0.f, rs1 = 0.f;
#pragma unroll
            for (int nt = 0; nt < 8; nt++) {
                sa[i][nt][0] = exp2f(sa[i][nt][0] - mn0); rs0 += sa[i][nt][0];
                sa[i][nt][1] = exp2f(sa[i][nt][1] - mn0); rs0 += sa[i][nt][1];
                sa[i][nt][2] = exp2f(sa[i][nt][2] - mn1); rs1 += sa[i][nt][2];
                sa[i][nt][3] = exp2f(sa[i][nt][3] - mn1); rs1 += sa[i][nt][3];
            }
            rs0 += __shfl_xor_sync(0xffffffffu, rs0, 1);
            rs0 += __shfl_xor_sync(0xffffffffu, rs0, 2);
            rs1 += __shfl_xor_sync(0xffffffffu, rs1, 1);
            rs1 += __shfl_xor_sync(0xffffffffu, rs1, 2);
            ls[i][0] = ls[i][0] * c0 + rs0;
            ls[i][1] = ls[i][1] * c1 + rs1;
#pragma unroll
            for (int nt = 0; nt < 8; nt++) {
                oa[i][nt][0] *= c0; oa[i][nt][1] *= c0;
                oa[i][nt][2] *= c1; oa[i][nt][3] *= c1;
            }
        }

        // ---- O += P @ V : P fragments built in-register via quad shuffles ----
#pragma unroll
        for (int kk = 0; kk < 8; kk++) {
            const int kb = kk * 8;
            uint32_t pa[2][4];
#pragma unroll
            for (int i = 0; i < 2; i++) {
                const float c0 = sa[i][kk][0], c1 = sa[i][kk][1];
                const float c2 = sa[i][kk][2], c3 = sa[i][kk][3];
                const float x0 = __shfl_sync(0xffffffffu, c0, lo);
                const float x1 = __shfl_sync(0xffffffffu, c1, lo);
                const float y0 = __shfl_sync(0xffffffffu, c2, lo);
                const float y1 = __shfl_sync(0xffffffffu, c3, lo);
                const float z0 = __shfl_sync(0xffffffffu, c0, hi);
                const float z1 = __shfl_sync(0xffffffffu, c1, hi);
                const float w0 = __shfl_sync(0xffffffffu, c2, hi);
                const float w1 = __shfl_sync(0xffffffffu, c3, hi);
                pa[i][0] = f2tf(odd ? x1 : x0);
                pa[i][1] = f2tf(odd ? y1 : y0);
                pa[i][2] = f2tf(odd ? z1 : z0);
                pa[i][3] = f2tf(odd ? w1 : w0);
            }
            uint32_t vf[4][4];
#pragma unroll
            for (int jj = 0; jj < 4; jj++)
                ldsm4(vf[jj], &Vt[(jj * 16 + ((lane >> 4) << 3) + (lane & 7)) * AS
                                  + kb + 4 * ((lane >> 3) & 1)]);
#pragma unroll
            for (int i = 0; i < 2; i++)
#pragma unroll
                for (int jj = 0; jj < 4; jj++) {
                    mma8(oa[i][2 * jj],     pa[i], &vf[jj][0]);
                    mma8(oa[i][2 * jj + 1], pa[i], &vf[jj][2]);
                }
        }
        buf ^= 1;
    }

    // ---- normalize + store tf32 into g_ao [M][768] ----
#pragma unroll
    for (int i = 0; i < 2; i++) {
        const float inv0 = 1.f / ls[i][0];
        const float inv1 = 1.f / ls[i][1];
        const int row = b * N_ + q0 + qbase + i * 16 + (lane >> 2);
        uint32_t* Op = O + (size_t)row * D_ + h * HD_;
#pragma unroll
        for (int nt = 0; nt < 8; nt++) {
            const int cc = nt * 8 + 2 * (lane & 3);
            *(uint2*)(Op + cc) =
                make_uint2(f2tf(oa[i][nt][0] * inv0), f2tf(oa[i][nt][1] * inv0));
            *(uint2*)(Op + (size_t)8 * D_ + cc) =
                make_uint2(f2tf(oa[i][nt][2] * inv1), f2tf(oa[i][nt][3] * inv1));
        }
    }
}

// ---------------------------------------------------------------------------
extern "C" void kernel_launch(void* const* d_in, const int* in_sizes, int n_in,
                              void* d_out, int out_size)
{
    const float* X  = (const float*)d_in[0];
    const float* Wq = (const float*)d_in[1];
    const float* bq = (const float*)d_in[2];
    const float* Wk = (const float*)d_in[3];
    const float* bk = (const float*)d_in[4];
    const float* Wv = (const float*)d_in[5];
    const float* bv = (const float*)d_in[6];
    const float* Wo = (const float*)d_in[7];
    const float* bo = (const float*)d_in[8];
    float* out = (float*)d_out;

    uint32_t *xt, *wqkvt, *wot, *qp, *kp, *vp, *aop;
    float* bqkv;
    cudaGetSymbolAddress((void**)&xt,    g_xt);
    cudaGetSymbolAddress((void**)&wqkvt, g_wqkvt);
    cudaGetSymbolAddress((void**)&wot,   g_wot);
    cudaGetSymbolAddress((void**)&bqkv,  g_bqkv);
    cudaGetSymbolAddress((void**)&qp,    g_q);
    cudaGetSymbolAddress((void**)&kp,    g_k);
    cudaGetSymbolAddress((void**)&vp,    g_v);
    cudaGetSymbolAddress((void**)&aop,   g_ao);

    cudaFuncSetAttribute(gemm2<1>, cudaFuncAttributeMaxDynamicSharedMemorySize, GEMM_SMEM);
    cudaFuncSetAttribute(gemm2<0>, cudaFuncAttributeMaxDynamicSharedMemorySize, GEMM_SMEM);
    cudaFuncSetAttribute(attn3,    cudaFuncAttributeMaxDynamicSharedMemorySize, ATTN_SMEM);

    prep_x<<<M_ * D_ / 1024, 256>>>(X, xt);
    prep_w<<<dim3(24, 24, 4), dim3(32, 8)>>>(Wq, Wk, Wv, Wo, wqkvt, wot);
    prep_b<<<1, D_>>>(bq, bk, bv, bqkv);

    gemm2<1><<<dim3(3 * D_ / 128, M_ / 128), 128, GEMM_SMEM>>>(
        xt, wqkvt, bqkv, nullptr, qp, kp, vp);

    attn3<<<dim3(N_ / 128, H_, B_), 128, ATTN_SMEM>>>(qp, kp, vp, aop);

    gemm2<0><<<dim3(D_ / 128, M_ / 128), 128, GEMM_SMEM>>>(
        aop, wot, bo, out, nullptr, nullptr, nullptr);
}

// round 7
// speedup vs baseline: 2.0404x; 1.7942x over previous
#include <cuda_runtime.h>
#include <cuda_fp16.h>
#include <stdint.h>
#include <math.h>

#define B_  16
#define N_  1024
#define D_  768
#define H_  12
#define HD_ 64
#define M_  (B_ * N_)            // 16384
#define SCALE2_ 0.05205928822087216f   // (1/sqrt(768)) * log2(e)

// ---- device scratch (no allocation in kernel_launch) ----
__device__ __half g_xt[M_ * D_];            // X in fp16
__device__ __half g_wqkvt[3 * D_ * D_];     // W_{q,k,v}^T  [n=2304][k=768] fp16
__device__ __half g_wot[D_ * D_];           // W_o^T        [n][k] fp16
__device__ float  g_bqkv[3 * D_];
__device__ __half g_q[B_ * H_ * N_ * HD_];  // [b][h][n][d] (scale*log2e folded)
__device__ __half g_k[B_ * H_ * N_ * HD_];  // [b][h][n][d]
__device__ __half g_v[B_ * H_ * HD_ * N_];  // [b][h][d][n] (transposed)
__device__ __half g_ao[M_ * D_];            // attn out

// ---------------------------------------------------------------------------
__device__ __forceinline__ uint32_t packh2(float lo, float hi) {
    uint32_t r;
    asm("cvt.rn.f16x2.f32 %0, %1, %2;" : "=r"(r) : "f"(hi), "f"(lo));
    return r;   // low 16 bits = lo, high = hi
}
__device__ __forceinline__ void mma16(float c[4], const uint32_t a[4],
                                      uint32_t b0, uint32_t b1) {
    asm volatile(
        "mma.sync.aligned.m16n8k16.row.col.f32.f16.f16.f32 "
        "{%0,%1,%2,%3}, {%4,%5,%6,%7}, {%8,%9}, {%0,%1,%2,%3};"
        : "+f"(c[0]), "+f"(c[1]), "+f"(c[2]), "+f"(c[3])
        : "r"(a[0]), "r"(a[1]), "r"(a[2]), "r"(a[3]), "r"(b0), "r"(b1));
}
__device__ __forceinline__ uint32_t smaddr(const void* p) {
    return (uint32_t)__cvta_generic_to_shared(p);
}
__device__ __forceinline__ void ldsm4(uint32_t r[4], const void* p) {
    uint32_t a = smaddr(p);
    asm volatile("ldmatrix.sync.aligned.m8n8.x4.shared.b16 {%0,%1,%2,%3}, [%4];"
                 : "=r"(r[0]), "=r"(r[1]), "=r"(r[2]), "=r"(r[3]) : "r"(a));
}
__device__ __forceinline__ void cp16(void* sp, const void* gp) {
    asm volatile("cp.async.cg.shared.global [%0], [%1], 16;"
                 :: "r"(smaddr(sp)), "l"(gp));
}
#define CP_COMMIT asm volatile("cp.async.commit_group;")
#define CP_WAIT0  asm volatile("cp.async.wait_group 0;")

// ---------------------------------------------------------------------------
// prep kernels (one-time)
// ---------------------------------------------------------------------------
__global__ void prep_x(const float* __restrict__ X, __half* __restrict__ Xt) {
    size_t i = ((size_t)blockIdx.x * 256 + threadIdx.x) * 4;
    float4 v = *(const float4*)(X + i);
    uint2 u = make_uint2(packh2(v.x, v.y), packh2(v.z, v.w));
    *(uint2*)(Xt + i) = u;
}

__global__ void prep_w(const float* __restrict__ Wq, const float* __restrict__ Wk,
                       const float* __restrict__ Wv, const float* __restrict__ Wo,
                       __half* __restrict__ Wqkvt, __half* __restrict__ Wot) {
    __shared__ float t[32][33];
    const int z = blockIdx.z;
    const float* src = (z == 0) ? Wq : (z == 1) ? Wk : (z == 2) ? Wv : Wo;
    __half* dst = (z < 3) ? (Wqkvt + (size_t)z * D_ * D_) : Wot;
    const int x0 = blockIdx.x * 32;   // n
    const int y0 = blockIdx.y * 32;   // k
    const int tx = threadIdx.x, ty = threadIdx.y;
#pragma unroll
    for (int r = 0; r < 4; r++)
        t[ty + 8 * r][tx] = src[(size_t)(y0 + ty + 8 * r) * D_ + x0 + tx];
    __syncthreads();
#pragma unroll
    for (int r = 0; r < 4; r++)
        dst[(size_t)(x0 + ty + 8 * r) * D_ + y0 + tx] = __float2half_rn(t[tx][ty + 8 * r]);
}

__global__ void prep_b(const float* bq, const float* bk, const float* bv, float* bqkv) {
    int i = threadIdx.x;
    bqkv[i] = bq[i]; bqkv[D_ + i] = bk[i]; bqkv[2 * D_ + i] = bv[i];
}

// ---------------------------------------------------------------------------
// fp16 HMMA GEMM: C = A(h [M][768]) @ Bt(h [N][768])^T + bias
// CTA 128x128, k-stage 64, single-sync double buffer, 4 warps (2x2),
// warp tile 64x64, m16n8k16.
// MODE 1: fused QKV epilogue -> g_q (scaled) / g_k / g_v(transposed), fp16.
// MODE 0: f32 out + bias (final projection).
// ---------------------------------------------------------------------------
#define HS 72                               // padded stride, halfs (144 B)
#define GEMM_STAGE_H (128 * HS)             // per A or B stage, halfs
#define GEMM_SMEM (4 * GEMM_STAGE_H * 2)    // 2 stages x (A+B) x 2B = 73728
#define NKT_ (D_ / 64)                      // 12 k-iters

template <int MODE>
__global__ __launch_bounds__(128)
void gemm3(const __half* __restrict__ A, const __half* __restrict__ Bt,
           const float* __restrict__ bias, float* __restrict__ outF,
           __half* __restrict__ oq, __half* __restrict__ ok,
           __half* __restrict__ ov)
{
    extern __shared__ __half sh[];

    const int tid  = threadIdx.x;
    const int lane = tid & 31;
    const int wid  = tid >> 5;
    const int wm   = (wid >> 1) * 64;
    const int wn   = (wid & 1) * 64;
    const int m0   = blockIdx.y * 128;
    const int n0   = blockIdx.x * 128;

    const int lr = tid >> 3;             // 0..15
    const int lc = (tid & 7) * 8;        // 0..56 (halfs)
    const __half* Ap = A  + (size_t)(m0 + lr) * D_ + lc;
    const __half* Bp = Bt + (size_t)(n0 + lr) * D_ + lc;

    float acc[4][8][4];
#pragma unroll
    for (int i = 0; i < 4; i++)
#pragma unroll
        for (int j = 0; j < 8; j++)
#pragma unroll
            for (int r = 0; r < 4; r++) acc[i][j][r] = 0.f;

    // fill stage s with k-tile t (64 halfs of k)
    auto fill = [&](int s, int t) {
        __half* as = sh + s * 2 * GEMM_STAGE_H;
        __half* bs = as + GEMM_STAGE_H;
#pragma unroll
        for (int p = 0; p < 8; p++) {
            const int row = lr + 16 * p;
            cp16(&as[row * HS + lc], Ap + (size_t)16 * p * D_ + t * 64);
            cp16(&bs[row * HS + lc], Bp + (size_t)16 * p * D_ + t * 64);
        }
    };

    fill(0, 0); CP_COMMIT;

    int buf = 0;
    for (int it = 0; it < NKT_; it++) {
        CP_WAIT0;            // tile it arrived
        __syncthreads();     // visible to all; prior reads of buf^1 done
        if (it + 1 < NKT_) {
            fill(buf ^ 1, it + 1);
            CP_COMMIT;
        }

        const __half* as = sh + buf * 2 * GEMM_STAGE_H;
        const __half* bs = as + GEMM_STAGE_H;
#pragma unroll
        for (int kk = 0; kk < 4; kk++) {
            const int kb = kk * 16;
            uint32_t af[4][4];
#pragma unroll
            for (int i = 0; i < 4; i++)
                ldsm4(af[i], &as[(wm + i * 16 + (lane & 15)) * HS + kb + 8 * (lane >> 4)]);
            uint32_t bf[4][4];
#pragma unroll
            for (int jj = 0; jj < 4; jj++)
                ldsm4(bf[jj], &bs[(wn + jj * 16 + ((lane >> 4) << 3) + (lane & 7)) * HS
                                  + kb + 8 * ((lane >> 3) & 1)]);
#pragma unroll
            for (int i = 0; i < 4; i++)
#pragma unroll
                for (int jj = 0; jj < 4; jj++) {
                    mma16(acc[i][2 * jj],     af[i], bf[jj][0], bf[jj][1]);
                    mma16(acc[i][2 * jj + 1], af[i], bf[jj][2], bf[jj][3]);
                }
        }
        buf ^= 1;
    }

    // epilogue: c0,c1 at (row, col..col+1); c2,c3 at (row+8, ...)
    const int mrow0 = m0 + wm + (lane >> 2);
    const int col0  = n0 + wn + 2 * (lane & 3);
#pragma unroll
    for (int i = 0; i < 4; i++) {
#pragma unroll
        for (int j = 0; j < 8; j++) {
            const int row = mrow0 + i * 16;
            const int col = col0 + j * 8;
            const float2 bv = *(const float2*)(bias + col);
            float c0 = acc[i][j][0] + bv.x, c1 = acc[i][j][1] + bv.y;
            float c2 = acc[i][j][2] + bv.x, c3 = acc[i][j][3] + bv.y;
            if (MODE == 0) {
                *(float2*)(outF + (size_t)row * D_ + col)       = make_float2(c0, c1);
                *(float2*)(outF + (size_t)(row + 8) * D_ + col) = make_float2(c2, c3);
            } else {
                const int which = n0 / D_;        // uniform per CTA
                const int ncol  = col - which * D_;
                const int h = ncol >> 6, d = ncol & 63;
                const int b = row >> 10, r = row & 1023;
                if (which == 0) {
                    __half* base = oq + ((((size_t)b * H_ + h) * N_) + r) * HD_ + d;
                    *(uint32_t*)base             = packh2(c0 * SCALE2_, c1 * SCALE2_);
                    *(uint32_t*)(base + 8 * HD_) = packh2(c2 * SCALE2_, c3 * SCALE2_);
                } else if (which == 1) {
                    __half* base = ok + ((((size_t)b * H_ + h) * N_) + r) * HD_ + d;
                    *(uint32_t*)base             = packh2(c0, c1);
                    *(uint32_t*)(base + 8 * HD_) = packh2(c2, c3);
                } else {
                    // V transposed: [b][h][d][key]
                    __half* base = ov + (((size_t)b * H_ + h) * HD_ + d) * N_ + r;
                    base[0]      = __float2half_rn(c0);
                    base[N_]     = __float2half_rn(c1);
                    base[8]      = __float2half_rn(c2);
                    base[N_ + 8] = __float2half_rn(c3);
                }
            }
        }
    }
}

// ---------------------------------------------------------------------------
// fp16 flash attention: CTA = 128 q rows, 128 threads (4 warps x 32 q rows).
// Double-buffered K/V; P stays in registers (pack S-frags -> PV A-frags).
// smem: Qs[128][72] + K[2][64][72] + Vt[2][64][72] halfs = 55296 B.
// ---------------------------------------------------------------------------
#define ATTN_SMEM ((128 + 2 * 64 + 2 * 64) * HS * 2)   // 55296 B

__global__ __launch_bounds__(128, 3)
void attn4(const __half* __restrict__ Q, const __half* __restrict__ K,
           const __half* __restrict__ V, __half* __restrict__ O)
{
    extern __shared__ __half sh[];
    __half* Qs = sh;                        // [128][HS]
    __half* Kb = sh + 128 * HS;             // [2][64][HS]
    __half* Vb = sh + (128 + 128) * HS;     // [2][64][HS]  ([d][key])

    const int tid  = threadIdx.x;
    const int lane = tid & 31;
    const int wid  = tid >> 5;
    const int b    = blockIdx.z;
    const int h    = blockIdx.y;
    const int q0   = blockIdx.x * 128;

    const __half* Qg = Q + (((size_t)b * H_ + h) * N_ + q0) * HD_;
    const __half* Kg = K + (((size_t)b * H_ + h) * N_) * HD_;
    const __half* Vg = V + (((size_t)b * H_ + h) * HD_) * N_;

    const int fr = tid >> 3;              // 0..15
    const int fc = (tid & 7) * 8;         // 0..56

    // prologue: Q (128x64) + K/V tile 0
#pragma unroll
    for (int p = 0; p < 8; p++) {
        const int row = fr + 16 * p;
        cp16(&Qs[row * HS + fc], Qg + (size_t)row * HD_ + fc);
    }
#pragma unroll
    for (int p = 0; p < 4; p++) {
        const int row = fr + 16 * p;
        cp16(&Kb[row * HS + fc], Kg + (size_t)row * HD_ + fc);
        cp16(&Vb[row * HS + fc], Vg + (size_t)row * N_ + fc);
    }
    CP_COMMIT;

    float oa[2][8][4];
    float ms[2][2], ls[2][2];
#pragma unroll
    for (int i = 0; i < 2; i++) {
        ms[i][0] = ms[i][1] = -1e30f;
        ls[i][0] = ls[i][1] = 0.f;
#pragma unroll
        for (int nt = 0; nt < 8; nt++)
#pragma unroll
            for (int r = 0; r < 4; r++) oa[i][nt][r] = 0.f;
    }

    const int qbase = wid * 32;

    int buf = 0;
    for (int t = 0; t < N_ / 64; t++) {
        CP_WAIT0;
        __syncthreads();

        if (t + 1 < N_ / 64) {
            __half* kd = Kb + (buf ^ 1) * 64 * HS;
            __half* vd = Vb + (buf ^ 1) * 64 * HS;
            const __half* kg = Kg + (size_t)(t + 1) * 64 * HD_;
            const __half* vg = Vg + (size_t)(t + 1) * 64;
#pragma unroll
            for (int p = 0; p < 4; p++) {
                const int row = fr + 16 * p;
                cp16(&kd[row * HS + fc], kg + (size_t)row * HD_ + fc);
                cp16(&vd[row * HS + fc], vg + (size_t)row * N_ + fc);
            }
            CP_COMMIT;
        }

        const __half* Kt = Kb + buf * 64 * HS;
        const __half* Vt = Vb + buf * 64 * HS;

        // ---- S = Q K^T (32 q x 64 keys per warp), 4 k16-steps over d ----
        float sa[2][8][4];
#pragma unroll
        for (int i = 0; i < 2; i++)
#pragma unroll
            for (int nt = 0; nt < 8; nt++)
#pragma unroll
                for (int r = 0; r < 4; r++) sa[i][nt][r] = 0.f;

#pragma unroll
        for (int kk = 0; kk < 4; kk++) {
            const int kb = kk * 16;
            uint32_t qa[2][4];
#pragma unroll
            for (int i = 0; i < 2; i++)
                ldsm4(qa[i], &Qs[(qbase + i * 16 + (lane & 15)) * HS + kb + 8 * (lane >> 4)]);
            uint32_t kf[4][4];
#pragma unroll
            for (int jj = 0; jj < 4; jj++)
                ldsm4(kf[jj], &Kt[(jj * 16 + ((lane >> 4) << 3) + (lane & 7)) * HS
                                  + kb + 8 * ((lane >> 3) & 1)]);
#pragma unroll
            for (int i = 0; i < 2; i++)
#pragma unroll
                for (int jj = 0; jj < 4; jj++) {
                    mma16(sa[i][2 * jj],     qa[i], kf[jj][0], kf[jj][1]);
                    mma16(sa[i][2 * jj + 1], qa[i], kf[jj][2], kf[jj][3]);
                }
        }

        // ---- online softmax (exp2 domain; log2e folded into Q) ----
#pragma unroll
        for (int i = 0; i < 2; i++) {
            float tm0 = -1e30f, tm1 = -1e30f;
#pragma unroll
            for (int nt = 0; nt < 8; nt++) {
                tm0 = fmaxf(tm0, fmaxf(sa[i][nt][0], sa[i][nt][1]));
                tm1 = fmaxf(tm1, fmaxf(sa[i][nt][2], sa[i][nt][3]));
            }
            tm0 = fmaxf(tm0, __shfl_xor_sync(0xffffffffu, tm0, 1));
            tm0 = fmaxf(tm0, __shfl_xor_sync(0xffffffffu, tm0, 2));
            tm1 = fmaxf(tm1, __shfl_xor_sync(0xffffffffu, tm1, 1));
            tm1 = fmaxf(tm1, __shfl_xor_sync(0xffffffffu, tm1, 2));
            const float mn0 = fmaxf(ms[i][0], tm0);
            const float mn1 = fmaxf(ms[i][1], tm1);
            const float c0 = exp2f(ms[i][0] - mn0);
            const float c1 = exp2f(ms[i][1] - mn1);
            ms[i][0] = mn0; ms[i][1] = mn1;
            float rs0 = 0.f, rs1 = 0.f;
#pragma unroll
            for (int nt = 0; nt < 8; nt++) {
                sa[i][nt][0] = exp2f(sa[i][nt][0] - mn0); rs0 += sa[i][nt][0];
                sa[i][nt][1] = exp2f(sa[i][nt][1] - mn0); rs0 += sa[i][nt][1];
                sa[i][nt][2] = exp2f(sa[i][nt][2] - mn1); rs1 += sa[i][nt][2];
                sa[i][nt][3] = exp2f(sa[i][nt][3] - mn1); rs1 += sa[i][nt][3];
            }
            rs0 += __shfl_xor_sync(0xffffffffu, rs0, 1);
            rs0 += __shfl_xor_sync(0xffffffffu, rs0, 2);
            rs1 += __shfl_xor_sync(0xffffffffu, rs1, 1);
            rs1 += __shfl_xor_sync(0xffffffffu, rs1, 2);
            ls[i][0] = ls[i][0] * c0 + rs0;
            ls[i][1] = ls[i][1] * c1 + rs1;
#pragma unroll
            for (int nt = 0; nt < 8; nt++) {
                oa[i][nt][0] *= c0; oa[i][nt][1] *= c0;
                oa[i][nt][2] *= c1; oa[i][nt][3] *= c1;
            }
        }

        // ---- O += P @ V : P A-frags are repacked S C-frags (no shuffle!) ----
#pragma unroll
        for (int kk = 0; kk < 4; kk++) {     // keys 16kk..16kk+15
            const int kb = kk * 16;
            uint32_t pa[2][4];
#pragma unroll
            for (int i = 0; i < 2; i++) {
                pa[i][0] = packh2(sa[i][2 * kk][0],     sa[i][2 * kk][1]);
                pa[i][1] = packh2(sa[i][2 * kk][2],     sa[i][2 * kk][3]);
                pa[i][2] = packh2(sa[i][2 * kk + 1][0], sa[i][2 * kk + 1][1]);
                pa[i][3] = packh2(sa[i][2 * kk + 1][2], sa[i][2 * kk + 1][3]);
            }
            uint32_t vf[4][4];
#pragma unroll
            for (int jj = 0; jj < 4; jj++)
                ldsm4(vf[jj], &Vt[(jj * 16 + ((lane >> 4) << 3) + (lane & 7)) * HS
                                  + kb + 8 * ((lane >> 3) & 1)]);
#pragma unroll
            for (int i = 0; i < 2; i++)
#pragma unroll
                for (int jj = 0; jj < 4; jj++) {
                    mma16(oa[i][2 * jj],     pa[i], vf[jj][0], vf[jj][1]);
                    mma16(oa[i][2 * jj + 1], pa[i], vf[jj][2], vf[jj][3]);
                }
        }
        buf ^= 1;
    }

    // ---- normalize + store fp16 into g_ao [M][768] ----
#pragma unroll
    for (int i = 0; i < 2; i++) {
        const float inv0 = 1.f / ls[i][0];
        const float inv1 = 1.f / ls[i][1];
        const int row = b * N_ + q0 + qbase + i * 16 + (lane >> 2);
        __half* Op = O + (size_t)row * D_ + h * HD_;
#pragma unroll
        for (int nt = 0; nt < 8; nt++) {
            const int cc = nt * 8 + 2 * (lane & 3);
            *(uint32_t*)(Op + cc) =
                packh2(oa[i][nt][0] * inv0, oa[i][nt][1] * inv0);
            *(uint32_t*)(Op + (size_t)8 * D_ + cc) =
                packh2(oa[i][nt][2] * inv1, oa[i][nt][3] * inv1);
        }
    }
}

// ---------------------------------------------------------------------------
extern "C" void kernel_launch(void* const* d_in, const int* in_sizes, int n_in,
                              void* d_out, int out_size)
{
    const float* X  = (const float*)d_in[0];
    const float* Wq = (const float*)d_in[1];
    const float* bq = (const float*)d_in[2];
    const float* Wk = (const float*)d_in[3];
    const float* bk = (const float*)d_in[4];
    const float* Wv = (const float*)d_in[5];
    const float* bv = (const float*)d_in[6];
    const float* Wo = (const float*)d_in[7];
    const float* bo = (const float*)d_in[8];
    float* out = (float*)d_out;

    __half *xt, *wqkvt, *wot, *qp, *kp, *vp, *aop;
    float* bqkv;
    cudaGetSymbolAddress((void**)&xt,    g_xt);
    cudaGetSymbolAddress((void**)&wqkvt, g_wqkvt);
    cudaGetSymbolAddress((void**)&wot,   g_wot);
    cudaGetSymbolAddress((void**)&bqkv,  g_bqkv);
    cudaGetSymbolAddress((void**)&qp,    g_q);
    cudaGetSymbolAddress((void**)&kp,    g_k);
    cudaGetSymbolAddress((void**)&vp,    g_v);
    cudaGetSymbolAddress((void**)&aop,   g_ao);

    cudaFuncSetAttribute(gemm3<1>, cudaFuncAttributeMaxDynamicSharedMemorySize, GEMM_SMEM);
    cudaFuncSetAttribute(gemm3<0>, cudaFuncAttributeMaxDynamicSharedMemorySize, GEMM_SMEM);
    cudaFuncSetAttribute(attn4,    cudaFuncAttributeMaxDynamicSharedMemorySize, ATTN_SMEM);

    prep_x<<<M_ * D_ / 1024, 256>>>(X, xt);
    prep_w<<<dim3(24, 24, 4), dim3(32, 8)>>>(Wq, Wk, Wv, Wo, wqkvt, wot);
    prep_b<<<1, D_>>>(bq, bk, bv, bqkv);

    gemm3<1><<<dim3(3 * D_ / 128, M_ / 128), 128, GEMM_SMEM>>>(
        xt, wqkvt, bqkv, nullptr, qp, kp, vp);

    attn4<<<dim3(N_ / 128, H_, B_), 128, ATTN_SMEM>>>(qp, kp, vp, aop);

    gemm3<0><<<dim3(D_ / 128, M_ / 128), 128, GEMM_SMEM>>>(
        aop, wot, bo, out, nullptr, nullptr, nullptr);
}